// round 1
// baseline (speedup 1.0000x reference)
#include <cuda_runtime.h>

#define NDIM 4096

// Inter-layer spike vectors (scratch via __device__ globals — no allocation).
__device__ float g_enc[NDIM];
__device__ float g_s0[NDIM];
__device__ float g_s1[NDIM];

// Rate-coding encoder: enc_i = (u_i < x_i) ? 1 : 0. Runs once, 16 KB traffic.
__global__ void enc_k(const float* __restrict__ x, const float* __restrict__ u) {
    int i = blockIdx.x * blockDim.x + threadIdx.x;
    if (i < NDIM) g_enc[i] = (u[i] < x[i]) ? 1.0f : 0.0f;
}

// Masked matvec + threshold. One row per block; 256 threads each sum 16
// elements via float4 loads of W and M (DRAM streaming) and the spike
// vector (L2-resident, 16 KB).
//  IN : 0 -> g_enc, 1 -> g_s0, 2 -> g_s1
//  OUT: 0 -> g_s0,  1 -> g_s1, 2 -> out[row] = spk / T
template<int IN, int OUT>
__global__ __launch_bounds__(256) void layer_k(const float* __restrict__ W,
                                               const float* __restrict__ M,
                                               const int* __restrict__ Tp,
                                               float* __restrict__ out) {
    const float* s = (IN == 0) ? g_enc : (IN == 1) ? g_s0 : g_s1;
    const int row = blockIdx.x;
    const float4* __restrict__ w4 = reinterpret_cast<const float4*>(W) + (size_t)row * (NDIM / 4);
    const float4* __restrict__ m4 = reinterpret_cast<const float4*>(M) + (size_t)row * (NDIM / 4);
    const float4* __restrict__ s4 = reinterpret_cast<const float4*>(s);

    float acc = 0.0f;
#pragma unroll
    for (int k = 0; k < (NDIM / 4) / 256; k++) {
        const int idx = threadIdx.x + k * 256;
        const float4 w  = w4[idx];
        const float4 m  = m4[idx];
        const float4 sv = s4[idx];
        acc = fmaf(w.x * m.x, sv.x, acc);
        acc = fmaf(w.y * m.y, sv.y, acc);
        acc = fmaf(w.z * m.z, sv.z, acc);
        acc = fmaf(w.w * m.w, sv.w, acc);
    }

    // Warp reduce
#pragma unroll
    for (int o = 16; o; o >>= 1) acc += __shfl_xor_sync(0xffffffffu, acc, o);

    __shared__ float sm[8];
    if ((threadIdx.x & 31) == 0) sm[threadIdx.x >> 5] = acc;
    __syncthreads();

    if (threadIdx.x == 0) {
        float t = 0.0f;
#pragma unroll
        for (int i = 0; i < 8; i++) t += sm[i];
        const float spk = (t > 1.0f) ? 1.0f : 0.0f;   // THRESH = 1.0, strict
        if (OUT == 0)      g_s0[row] = spk;
        else if (OUT == 1) g_s1[row] = spk;
        else {
            const int T = Tp ? *Tp : 128;
            out[row] = spk / (float)T;                // spikes only at t=0 -> mean = spk/T
        }
    }
}

extern "C" void kernel_launch(void* const* d_in, const int* in_sizes, int n_in,
                              void* d_out, int out_size) {
    const float* x  = (const float*)d_in[0];
    const float* u  = (const float*)d_in[1];
    const float* W0 = (const float*)d_in[2];
    const float* W1 = (const float*)d_in[3];
    const float* W2 = (const float*)d_in[4];
    const float* M0 = (const float*)d_in[5];
    const float* M1 = (const float*)d_in[6];
    const float* M2 = (const float*)d_in[7];
    const int*   T  = (n_in > 8) ? (const int*)d_in[8] : nullptr;
    float* out = (float*)d_out;

    enc_k<<<NDIM / 256, 256>>>(x, u);
    layer_k<0, 0><<<NDIM, 256>>>(W0, M0, nullptr, nullptr);
    layer_k<1, 1><<<NDIM, 256>>>(W1, M1, nullptr, nullptr);
    layer_k<2, 2><<<NDIM, 256>>>(W2, M2, T, out);
}